// round 1
// baseline (speedup 1.0000x reference)
#include <cuda_runtime.h>
#include <math.h>

#define B_    1024
#define N_    128
#define DIN_  256
#define HID_  256
#define DOUT_ 256
#define KDIM_ 512

// ---------------- scratch (static device globals; no allocation) ----------------
__device__ float g_q[(size_t)B_ * N_ * KDIM_];   // 268 MB
__device__ float g_k[(size_t)B_ * N_ * KDIM_];   // 268 MB
__device__ float g_v[(size_t)B_ * N_ * HID_];    // 134 MB
__device__ float g_ctx[(size_t)B_ * N_ * HID_];  // 134 MB

// =================================================================================
// K1: fused QKV projection.  C[m, :] = relu(x[m, :] @ W + b) for W in {Wv, Wq, Wk}
// Grid: (1024 M-tiles, 10 N-tiles of 128 cols: 2 for V, 4 for Q, 4 for K)
// Classic 128x128x16 SGEMM, 256 threads, 8x8 register tile per thread.
// =================================================================================
__global__ __launch_bounds__(256) void qkv_kernel(
    const float* __restrict__ x,
    const float* __restrict__ Wv, const float* __restrict__ bv,
    const float* __restrict__ Wq, const float* __restrict__ bq,
    const float* __restrict__ Wk, const float* __restrict__ bk)
{
    __shared__ float As[16][132];   // A tile transposed: As[k][m]
    __shared__ float Bs[16][132];   // B tile: Bs[k][n]

    const int mt = blockIdx.x;
    const int nt = blockIdx.y;

    const float* W; const float* bias; float* out; int wld; int c0;
    if (nt < 2)      { W = Wv; bias = bv; out = g_v; wld = HID_;  c0 = nt * 128; }
    else if (nt < 6) { W = Wq; bias = bq; out = g_q; wld = KDIM_; c0 = (nt - 2) * 128; }
    else             { W = Wk; bias = bk; out = g_k; wld = KDIM_; c0 = (nt - 6) * 128; }

    const int tid = threadIdx.x;
    const int tx = tid & 15;
    const int ty = tid >> 4;

    float acc[8][8];
    #pragma unroll
    for (int i = 0; i < 8; i++)
        #pragma unroll
        for (int j = 0; j < 8; j++) acc[i][j] = 0.f;

    const float* A = x + (size_t)mt * 128 * DIN_;

    for (int k0 = 0; k0 < DIN_; k0 += 16) {
        #pragma unroll
        for (int it = 0; it < 2; it++) {
            int idx = tid * 2 + it;          // 0..511
            int m  = idx >> 2;               // 0..127
            int kq = (idx & 3) << 2;         // 0,4,8,12
            float4 t4 = *reinterpret_cast<const float4*>(A + (size_t)m * DIN_ + k0 + kq);
            As[kq + 0][m] = t4.x; As[kq + 1][m] = t4.y;
            As[kq + 2][m] = t4.z; As[kq + 3][m] = t4.w;
        }
        #pragma unroll
        for (int it = 0; it < 2; it++) {
            int idx = tid * 2 + it;          // 0..511
            int kr = idx >> 5;               // 0..15
            int nq = (idx & 31) << 2;        // 0..124
            *reinterpret_cast<float4*>(&Bs[kr][nq]) =
                *reinterpret_cast<const float4*>(W + (size_t)(k0 + kr) * wld + c0 + nq);
        }
        __syncthreads();

        #pragma unroll
        for (int kk = 0; kk < 16; kk++) {
            float4 a0 = *reinterpret_cast<const float4*>(&As[kk][ty * 8]);
            float4 a1 = *reinterpret_cast<const float4*>(&As[kk][ty * 8 + 4]);
            float4 b0 = *reinterpret_cast<const float4*>(&Bs[kk][tx * 8]);
            float4 b1 = *reinterpret_cast<const float4*>(&Bs[kk][tx * 8 + 4]);
            float a[8] = {a0.x, a0.y, a0.z, a0.w, a1.x, a1.y, a1.z, a1.w};
            float b[8] = {b0.x, b0.y, b0.z, b0.w, b1.x, b1.y, b1.z, b1.w};
            #pragma unroll
            for (int i = 0; i < 8; i++)
                #pragma unroll
                for (int j = 0; j < 8; j++) acc[i][j] += a[i] * b[j];
        }
        __syncthreads();
    }

    #pragma unroll
    for (int i = 0; i < 8; i++) {
        size_t m = (size_t)mt * 128 + ty * 8 + i;
        int cc = c0 + tx * 8;
        float4 r0, r1;
        r0.x = fmaxf(acc[i][0] + bias[cc + 0], 0.f);
        r0.y = fmaxf(acc[i][1] + bias[cc + 1], 0.f);
        r0.z = fmaxf(acc[i][2] + bias[cc + 2], 0.f);
        r0.w = fmaxf(acc[i][3] + bias[cc + 3], 0.f);
        r1.x = fmaxf(acc[i][4] + bias[cc + 4], 0.f);
        r1.y = fmaxf(acc[i][5] + bias[cc + 5], 0.f);
        r1.z = fmaxf(acc[i][6] + bias[cc + 6], 0.f);
        r1.w = fmaxf(acc[i][7] + bias[cc + 7], 0.f);
        *reinterpret_cast<float4*>(out + m * wld + cc)     = r0;
        *reinterpret_cast<float4*>(out + m * wld + cc + 4) = r1;
    }
}

// =================================================================================
// K2: per-batch attention. One CTA per batch b:
//   scores = q[b] @ k[b]^T  (128x128x512)
//   val = mask*(s+1000) - 1000 ; softmax rows ; att -> global + smem (transposed)
//   ctx = att @ v[b]  (128x256x128) -> g_ctx
// Dynamic smem ~94 KB -> 2 CTAs/SM.
// =================================================================================
#define ATTN_SMEM_FLOATS (128*132 + 16*132 + 16*132 + 128*16 + 256)
#define ATTN_SMEM_BYTES  (ATTN_SMEM_FLOATS * 4)

__global__ __launch_bounds__(256) void attn_kernel(
    const float* __restrict__ mask, float* __restrict__ att_out)
{
    extern __shared__ float sm[];
    float* attT = sm;                    // 128*132 : att transposed, attT[m][n]
    float* As   = attT + 128 * 132;      // 16*132
    float* Bs   = As   + 16 * 132;       // 16*132
    float* red  = Bs   + 16 * 132;       // 128*16
    float* smax = red  + 128 * 16;       // 128
    float* ssum = smax + 128;            // 128

    const int b   = blockIdx.x;
    const int tid = threadIdx.x;
    const int tx  = tid & 15;
    const int ty  = tid >> 4;

    const float* qb = g_q + (size_t)b * N_ * KDIM_;
    const float* kb = g_k + (size_t)b * N_ * KDIM_;
    const float* vb = g_v + (size_t)b * N_ * HID_;

    float acc[8][8];
    #pragma unroll
    for (int i = 0; i < 8; i++)
        #pragma unroll
        for (int j = 0; j < 8; j++) acc[i][j] = 0.f;

    // ---- scores = q @ k^T ----
    for (int k0 = 0; k0 < KDIM_; k0 += 16) {
        #pragma unroll
        for (int it = 0; it < 2; it++) {
            int idx = tid * 2 + it;
            int m  = idx >> 2;
            int kq = (idx & 3) << 2;
            float4 t4 = *reinterpret_cast<const float4*>(qb + (size_t)m * KDIM_ + k0 + kq);
            As[(kq + 0) * 132 + m] = t4.x; As[(kq + 1) * 132 + m] = t4.y;
            As[(kq + 2) * 132 + m] = t4.z; As[(kq + 3) * 132 + m] = t4.w;
            float4 u4 = *reinterpret_cast<const float4*>(kb + (size_t)m * KDIM_ + k0 + kq);
            Bs[(kq + 0) * 132 + m] = u4.x; Bs[(kq + 1) * 132 + m] = u4.y;
            Bs[(kq + 2) * 132 + m] = u4.z; Bs[(kq + 3) * 132 + m] = u4.w;
        }
        __syncthreads();
        #pragma unroll
        for (int kk = 0; kk < 16; kk++) {
            float4 a0 = *reinterpret_cast<const float4*>(&As[kk * 132 + ty * 8]);
            float4 a1 = *reinterpret_cast<const float4*>(&As[kk * 132 + ty * 8 + 4]);
            float4 b0 = *reinterpret_cast<const float4*>(&Bs[kk * 132 + tx * 8]);
            float4 b1 = *reinterpret_cast<const float4*>(&Bs[kk * 132 + tx * 8 + 4]);
            float a[8] = {a0.x, a0.y, a0.z, a0.w, a1.x, a1.y, a1.z, a1.w};
            float bb[8] = {b0.x, b0.y, b0.z, b0.w, b1.x, b1.y, b1.z, b1.w};
            #pragma unroll
            for (int i = 0; i < 8; i++)
                #pragma unroll
                for (int j = 0; j < 8; j++) acc[i][j] += a[i] * bb[j];
        }
        __syncthreads();
    }

    // ---- mask: val = m*(s+1000) - 1000  (m in {0,1}) ----
    const float* mb = mask + (size_t)b * N_ * N_;
    #pragma unroll
    for (int i = 0; i < 8; i++) {
        int r = ty * 8 + i;
        float4 m0 = *reinterpret_cast<const float4*>(mb + (size_t)r * N_ + tx * 8);
        float4 m1 = *reinterpret_cast<const float4*>(mb + (size_t)r * N_ + tx * 8 + 4);
        float mm[8] = {m0.x, m0.y, m0.z, m0.w, m1.x, m1.y, m1.z, m1.w};
        #pragma unroll
        for (int j = 0; j < 8; j++)
            acc[i][j] = mm[j] * (acc[i][j] + 1000.f) - 1000.f;
    }

    // ---- softmax over columns (axis 2) ----
    #pragma unroll
    for (int i = 0; i < 8; i++) {
        float lm = acc[i][0];
        #pragma unroll
        for (int j = 1; j < 8; j++) lm = fmaxf(lm, acc[i][j]);
        red[(ty * 8 + i) * 16 + tx] = lm;
    }
    __syncthreads();
    if (tid < 128) {
        float m = red[tid * 16];
        #pragma unroll
        for (int t = 1; t < 16; t++) m = fmaxf(m, red[tid * 16 + t]);
        smax[tid] = m;
    }
    __syncthreads();
    #pragma unroll
    for (int i = 0; i < 8; i++) {
        int r = ty * 8 + i;
        float mx = smax[r];
        float ls = 0.f;
        #pragma unroll
        for (int j = 0; j < 8; j++) {
            float e = __expf(acc[i][j] - mx);
            acc[i][j] = e;
            ls += e;
        }
        red[r * 16 + tx] = ls;
    }
    __syncthreads();
    if (tid < 128) {
        float s = 0.f;
        #pragma unroll
        for (int t = 0; t < 16; t++) s += red[tid * 16 + t];
        ssum[tid] = 1.f / s;
    }
    __syncthreads();

    float* ab = att_out + (size_t)b * N_ * N_;
    #pragma unroll
    for (int i = 0; i < 8; i++) {
        int r = ty * 8 + i;
        float inv = ssum[r];
        float o[8];
        #pragma unroll
        for (int j = 0; j < 8; j++) {
            float a = acc[i][j] * inv;
            o[j] = a;
            attT[(tx * 8 + j) * 132 + r] = a;   // transposed for GEMM2
        }
        float4 w0 = {o[0], o[1], o[2], o[3]};
        float4 w1 = {o[4], o[5], o[6], o[7]};
        *reinterpret_cast<float4*>(ab + (size_t)r * N_ + tx * 8)     = w0;
        *reinterpret_cast<float4*>(ab + (size_t)r * N_ + tx * 8 + 4) = w1;
    }
    __syncthreads();

    // ---- ctx = att @ v : [128,128] @ [128,256], two 128-col halves ----
    float* cb = g_ctx + (size_t)b * N_ * HID_;
    for (int half = 0; half < 2; half++) {
        int h0 = half * 128;
        float acc2[8][8];
        #pragma unroll
        for (int i = 0; i < 8; i++)
            #pragma unroll
            for (int j = 0; j < 8; j++) acc2[i][j] = 0.f;

        for (int kt = 0; kt < 8; kt++) {
            __syncthreads();   // previous Bs consumers done
            #pragma unroll
            for (int it = 0; it < 2; it++) {
                int idx = tid * 2 + it;
                int kr = idx >> 5;
                int nq = (idx & 31) << 2;
                *reinterpret_cast<float4*>(&Bs[kr * 132 + nq]) =
                    *reinterpret_cast<const float4*>(vb + (size_t)(kt * 16 + kr) * HID_ + h0 + nq);
            }
            __syncthreads();
            #pragma unroll
            for (int kk = 0; kk < 16; kk++) {
                float4 a0 = *reinterpret_cast<const float4*>(&attT[(kt * 16 + kk) * 132 + ty * 8]);
                float4 a1 = *reinterpret_cast<const float4*>(&attT[(kt * 16 + kk) * 132 + ty * 8 + 4]);
                float4 b0 = *reinterpret_cast<const float4*>(&Bs[kk * 132 + tx * 8]);
                float4 b1 = *reinterpret_cast<const float4*>(&Bs[kk * 132 + tx * 8 + 4]);
                float a[8] = {a0.x, a0.y, a0.z, a0.w, a1.x, a1.y, a1.z, a1.w};
                float bb[8] = {b0.x, b0.y, b0.z, b0.w, b1.x, b1.y, b1.z, b1.w};
                #pragma unroll
                for (int i = 0; i < 8; i++)
                    #pragma unroll
                    for (int j = 0; j < 8; j++) acc2[i][j] += a[i] * bb[j];
            }
        }
        #pragma unroll
        for (int i = 0; i < 8; i++) {
            int r = ty * 8 + i;
            float4 w0 = {acc2[i][0], acc2[i][1], acc2[i][2], acc2[i][3]};
            float4 w1 = {acc2[i][4], acc2[i][5], acc2[i][6], acc2[i][7]};
            *reinterpret_cast<float4*>(cb + (size_t)r * HID_ + h0 + tx * 8)     = w0;
            *reinterpret_cast<float4*>(cb + (size_t)r * HID_ + h0 + tx * 8 + 4) = w1;
        }
    }
}

// =================================================================================
// K3: out = relu(ctx @ Wo + bo) -> d_out (first region)
// Grid: (1024 M-tiles, 2 N-tiles)
// =================================================================================
__global__ __launch_bounds__(256) void out_kernel(
    const float* __restrict__ Wo, const float* __restrict__ bo,
    float* __restrict__ out)
{
    __shared__ float As[16][132];
    __shared__ float Bs[16][132];

    const int mt = blockIdx.x;
    const int c0 = blockIdx.y * 128;

    const int tid = threadIdx.x;
    const int tx = tid & 15;
    const int ty = tid >> 4;

    float acc[8][8];
    #pragma unroll
    for (int i = 0; i < 8; i++)
        #pragma unroll
        for (int j = 0; j < 8; j++) acc[i][j] = 0.f;

    const float* A = g_ctx + (size_t)mt * 128 * HID_;

    for (int k0 = 0; k0 < HID_; k0 += 16) {
        #pragma unroll
        for (int it = 0; it < 2; it++) {
            int idx = tid * 2 + it;
            int m  = idx >> 2;
            int kq = (idx & 3) << 2;
            float4 t4 = *reinterpret_cast<const float4*>(A + (size_t)m * HID_ + k0 + kq);
            As[kq + 0][m] = t4.x; As[kq + 1][m] = t4.y;
            As[kq + 2][m] = t4.z; As[kq + 3][m] = t4.w;
        }
        #pragma unroll
        for (int it = 0; it < 2; it++) {
            int idx = tid * 2 + it;
            int kr = idx >> 5;
            int nq = (idx & 31) << 2;
            *reinterpret_cast<float4*>(&Bs[kr][nq]) =
                *reinterpret_cast<const float4*>(Wo + (size_t)(k0 + kr) * DOUT_ + c0 + nq);
        }
        __syncthreads();
        #pragma unroll
        for (int kk = 0; kk < 16; kk++) {
            float4 a0 = *reinterpret_cast<const float4*>(&As[kk][ty * 8]);
            float4 a1 = *reinterpret_cast<const float4*>(&As[kk][ty * 8 + 4]);
            float4 b0 = *reinterpret_cast<const float4*>(&Bs[kk][tx * 8]);
            float4 b1 = *reinterpret_cast<const float4*>(&Bs[kk][tx * 8 + 4]);
            float a[8] = {a0.x, a0.y, a0.z, a0.w, a1.x, a1.y, a1.z, a1.w};
            float b[8] = {b0.x, b0.y, b0.z, b0.w, b1.x, b1.y, b1.z, b1.w};
            #pragma unroll
            for (int i = 0; i < 8; i++)
                #pragma unroll
                for (int j = 0; j < 8; j++) acc[i][j] += a[i] * b[j];
        }
        __syncthreads();
    }

    #pragma unroll
    for (int i = 0; i < 8; i++) {
        size_t m = (size_t)mt * 128 + ty * 8 + i;
        int cc = c0 + tx * 8;
        float4 r0, r1;
        r0.x = fmaxf(acc[i][0] + bo[cc + 0], 0.f);
        r0.y = fmaxf(acc[i][1] + bo[cc + 1], 0.f);
        r0.z = fmaxf(acc[i][2] + bo[cc + 2], 0.f);
        r0.w = fmaxf(acc[i][3] + bo[cc + 3], 0.f);
        r1.x = fmaxf(acc[i][4] + bo[cc + 4], 0.f);
        r1.y = fmaxf(acc[i][5] + bo[cc + 5], 0.f);
        r1.z = fmaxf(acc[i][6] + bo[cc + 6], 0.f);
        r1.w = fmaxf(acc[i][7] + bo[cc + 7], 0.f);
        *reinterpret_cast<float4*>(out + m * DOUT_ + cc)     = r0;
        *reinterpret_cast<float4*>(out + m * DOUT_ + cc + 4) = r1;
    }
}

// =================================================================================
// Launch
// =================================================================================
extern "C" void kernel_launch(void* const* d_in, const int* in_sizes, int n_in,
                              void* d_out, int out_size)
{
    const float* x    = (const float*)d_in[0];
    const float* mask = (const float*)d_in[1];
    const float* Wv   = (const float*)d_in[2];
    const float* bv   = (const float*)d_in[3];
    const float* Wq   = (const float*)d_in[4];
    const float* bq   = (const float*)d_in[5];
    const float* Wk   = (const float*)d_in[6];
    const float* bk   = (const float*)d_in[7];
    const float* Wo   = (const float*)d_in[8];
    const float* bo   = (const float*)d_in[9];

    float* out     = (float*)d_out;
    float* att_out = out + (size_t)B_ * N_ * DOUT_;

    cudaFuncSetAttribute(attn_kernel,
                         cudaFuncAttributeMaxDynamicSharedMemorySize,
                         ATTN_SMEM_BYTES);

    qkv_kernel<<<dim3(1024, 10), 256>>>(x, Wv, bv, Wq, bq, Wk, bk);
    attn_kernel<<<1024, 256, ATTN_SMEM_BYTES>>>(mask, att_out);
    out_kernel<<<dim3(1024, 2), 256>>>(Wo, bo, out);
}

// round 4
// speedup vs baseline: 2.3408x; 2.3408x over previous
#include <cuda_runtime.h>
#include <cuda_bf16.h>
#include <cstdint>

#define B_    1024
#define N_    128
#define DIN_  256
#define HID_  256
#define DOUT_ 256
#define KDIM_ 512

// ---------------- scratch (static device globals; no allocation) ----------------
__device__ float g_q[(size_t)B_ * N_ * KDIM_];
__device__ float g_k[(size_t)B_ * N_ * KDIM_];
__device__ float g_v[(size_t)B_ * N_ * HID_];
__device__ float g_ctx[(size_t)B_ * N_ * HID_];

// ================================================================================
// helpers: mma.sync bf16 (sm_80+ baseline PTX -> compiles for plain sm_103)
// ================================================================================
__device__ __forceinline__ uint32_t smem_u32(const void* p) {
    uint32_t a;
    asm("{ .reg .u64 t; cvta.to.shared.u64 t, %1; cvt.u32.u64 %0, t; }" : "=r"(a) : "l"(p));
    return a;
}

__device__ __forceinline__ void ldm_x4(uint32_t* r, uint32_t addr) {
    asm volatile("ldmatrix.sync.aligned.m8n8.x4.shared.b16 {%0,%1,%2,%3}, [%4];"
                 : "=r"(r[0]), "=r"(r[1]), "=r"(r[2]), "=r"(r[3]) : "r"(addr));
}
__device__ __forceinline__ void ldm_x2(uint32_t* r, uint32_t addr) {
    asm volatile("ldmatrix.sync.aligned.m8n8.x2.shared.b16 {%0,%1}, [%2];"
                 : "=r"(r[0]), "=r"(r[1]) : "r"(addr));
}
__device__ __forceinline__ void mma_bf16(float* c, const uint32_t* a, const uint32_t* b) {
    asm volatile(
        "mma.sync.aligned.m16n8k16.row.col.f32.bf16.bf16.f32 "
        "{%0,%1,%2,%3}, {%4,%5,%6,%7}, {%8,%9}, {%0,%1,%2,%3};"
        : "+f"(c[0]), "+f"(c[1]), "+f"(c[2]), "+f"(c[3])
        : "r"(a[0]), "r"(a[1]), "r"(a[2]), "r"(a[3]), "r"(b[0]), "r"(b[1]));
}

// split fp32 pair -> bf16x2 hi (ret) + bf16x2 lo (out param)
__device__ __forceinline__ uint32_t pack_hilo(float x, float y, uint32_t& lo_out) {
    __nv_bfloat162 h = __floats2bfloat162_rn(x, y);
    float lx = x - __low2float(h);
    float ly = y - __high2float(h);
    __nv_bfloat162 l = __floats2bfloat162_rn(lx, ly);
    lo_out = *reinterpret_cast<uint32_t*>(&l);
    return *reinterpret_cast<uint32_t*>(&h);
}

// ================================================================================
// Projection GEMM body: O[128, c0:c0+128] = relu(A[128,256] @ W[256,wld] + bias)
// bf16 2-term split, 3 passes. smem: aHi/aLo/bHi/bLo 16KB each + wstag 33KB.
// Tiles stored swizzled: row stride 128B (64 halves, 8 granules of 16B),
// physical granule = g ^ (row & 7)  -> conflict-free ldmatrix.
// ================================================================================
#define PROJ_SMEM (4 * 16384 + 64 * 132 * 4)

__device__ __forceinline__ void gemm_proj(
    const float* __restrict__ A, const float* __restrict__ W,
    const float* __restrict__ bias, float* __restrict__ O, int wld, int c0)
{
    extern __shared__ char sm[];
    char* aHi = sm;
    char* aLo = sm + 16384;
    char* bHi = sm + 32768;
    char* bLo = sm + 49152;
    float* wst = (float*)(sm + 65536);       // [64][132]

    const int tid  = threadIdx.x;
    const int lane = tid & 31;
    const int wid  = tid >> 5;
    const int wm   = wid >> 2;               // 0..1 -> 64 rows
    const int wn   = wid & 3;                // 0..3 -> 32 cols
    const int l15  = lane & 15;
    const int l7   = lane & 7;
    const int gA   = lane >> 4;
    const int gB   = (lane >> 3) & 1;

    const uint32_t aHiB = smem_u32(aHi), bHiB = smem_u32(bHi);

    uint32_t rowA[4], rowB[4];
    #pragma unroll
    for (int mf = 0; mf < 4; mf++) rowA[mf] = (uint32_t)((wm * 64 + mf * 16 + l15) * 128);
    #pragma unroll
    for (int nf = 0; nf < 4; nf++) rowB[nf] = (uint32_t)((wn * 32 + nf * 8 + l7) * 128);

    float c[4][4][4];
    #pragma unroll
    for (int i = 0; i < 4; i++)
        #pragma unroll
        for (int j = 0; j < 4; j++)
            #pragma unroll
            for (int t = 0; t < 4; t++) c[i][j][t] = 0.f;

    for (int ch = 0; ch < 4; ch++) {
        // ---- stage A chunk [128][64] -> hi/lo swizzled ----
        #pragma unroll
        for (int i = 0; i < 4; i++) {
            int G = tid + i * 256;
            int m = G >> 3, g = G & 7;
            const float* p = A + (size_t)m * 256 + ch * 64 + g * 8;
            float4 v0 = *(const float4*)p;
            float4 v1 = *(const float4*)(p + 4);
            uint4 hi, lo;
            hi.x = pack_hilo(v0.x, v0.y, lo.x);
            hi.y = pack_hilo(v0.z, v0.w, lo.y);
            hi.z = pack_hilo(v1.x, v1.y, lo.z);
            hi.w = pack_hilo(v1.z, v1.w, lo.w);
            uint32_t off = (uint32_t)(m * 128 + ((g ^ (m & 7)) << 4));
            *(uint4*)(aHi + off) = hi;
            *(uint4*)(aLo + off) = lo;
        }
        // ---- stage W chunk [64][128] fp32 coalesced ----
        #pragma unroll
        for (int i = 0; i < 8; i++) {
            int idx = tid + i * 256;
            int kr = idx >> 5, nq = (idx & 31) << 2;
            *(float4*)(wst + kr * 132 + nq) =
                *(const float4*)(W + (size_t)(ch * 64 + kr) * wld + c0 + nq);
        }
        __syncthreads();
        // ---- transpose+convert: B[n][k] = W[k][c0+n] ----
        {
            int n = tid & 127;
            int ks2 = tid >> 7;              // 0..1
            #pragma unroll
            for (int j = 0; j < 4; j++) {
                int g = ks2 * 4 + j;
                int kb = g * 8;
                float v[8];
                #pragma unroll
                for (int t = 0; t < 8; t++) v[t] = wst[(kb + t) * 132 + n];
                uint4 hi, lo;
                hi.x = pack_hilo(v[0], v[1], lo.x);
                hi.y = pack_hilo(v[2], v[3], lo.y);
                hi.z = pack_hilo(v[4], v[5], lo.z);
                hi.w = pack_hilo(v[6], v[7], lo.w);
                uint32_t off = (uint32_t)(n * 128 + ((g ^ (n & 7)) << 4));
                *(uint4*)(bHi + off) = hi;
                *(uint4*)(bLo + off) = lo;
            }
        }
        __syncthreads();
        // ---- MMA: 4 k16-steps x 3 passes ----
        #pragma unroll
        for (int ks = 0; ks < 4; ks++) {
            uint32_t pa = (uint32_t)((((ks << 1) + gA) ^ l7) << 4);
            uint32_t pb = (uint32_t)((((ks << 1) + gB) ^ l7) << 4);
            uint32_t a[4][4], b[4][2];
            #pragma unroll
            for (int mf = 0; mf < 4; mf++) ldm_x4(a[mf], aHiB + rowA[mf] + pa);
            #pragma unroll
            for (int nf = 0; nf < 4; nf++) ldm_x2(b[nf], bHiB + rowB[nf] + pb);
            #pragma unroll
            for (int mf = 0; mf < 4; mf++)
                #pragma unroll
                for (int nf = 0; nf < 4; nf++) mma_bf16(c[mf][nf], a[mf], b[nf]);
            #pragma unroll
            for (int nf = 0; nf < 4; nf++) ldm_x2(b[nf], bHiB + 16384 + rowB[nf] + pb); // bLo
            #pragma unroll
            for (int mf = 0; mf < 4; mf++)
                #pragma unroll
                for (int nf = 0; nf < 4; nf++) mma_bf16(c[mf][nf], a[mf], b[nf]);
            #pragma unroll
            for (int mf = 0; mf < 4; mf++) ldm_x4(a[mf], aHiB + 16384 + rowA[mf] + pa); // aLo
            #pragma unroll
            for (int nf = 0; nf < 4; nf++) ldm_x2(b[nf], bHiB + rowB[nf] + pb);
            #pragma unroll
            for (int mf = 0; mf < 4; mf++)
                #pragma unroll
                for (int nf = 0; nf < 4; nf++) mma_bf16(c[mf][nf], a[mf], b[nf]);
        }
        __syncthreads();
    }

    // ---- epilogue: bias + relu, float2 stores ----
    #pragma unroll
    for (int mf = 0; mf < 4; mf++) {
        int row = wm * 64 + mf * 16 + (lane >> 2);
        #pragma unroll
        for (int nf = 0; nf < 4; nf++) {
            int col = c0 + wn * 32 + nf * 8 + ((lane & 3) << 1);
            float b0 = __ldg(bias + col), b1 = __ldg(bias + col + 1);
            float2 o0 = {fmaxf(c[mf][nf][0] + b0, 0.f), fmaxf(c[mf][nf][1] + b1, 0.f)};
            float2 o1 = {fmaxf(c[mf][nf][2] + b0, 0.f), fmaxf(c[mf][nf][3] + b1, 0.f)};
            *(float2*)(O + (size_t)row * wld + col)       = o0;
            *(float2*)(O + (size_t)(row + 8) * wld + col) = o1;
        }
    }
}

__global__ __launch_bounds__(256, 2) void qkv_tc(
    const float* __restrict__ x,
    const float* __restrict__ Wv, const float* __restrict__ bv,
    const float* __restrict__ Wq, const float* __restrict__ bq,
    const float* __restrict__ Wk, const float* __restrict__ bk)
{
    const int nt = blockIdx.x;
    const int mt = blockIdx.y;
    const float* W; const float* bias; float* out; int wld; int c0;
    if (nt < 2)      { W = Wv; bias = bv; out = g_v; wld = HID_;  c0 = nt * 128; }
    else if (nt < 6) { W = Wq; bias = bq; out = g_q; wld = KDIM_; c0 = (nt - 2) * 128; }
    else             { W = Wk; bias = bk; out = g_k; wld = KDIM_; c0 = (nt - 6) * 128; }
    gemm_proj(x + (size_t)mt * 128 * DIN_, W, bias, out + (size_t)mt * 128 * wld, wld, c0);
}

__global__ __launch_bounds__(256, 2) void out_tc(
    const float* __restrict__ Wo, const float* __restrict__ bo, float* __restrict__ out)
{
    const int nt = blockIdx.x;
    const int mt = blockIdx.y;
    gemm_proj(g_ctx + (size_t)mt * 128 * HID_, Wo, bo,
              out + (size_t)mt * 128 * DOUT_, DOUT_, nt * 128);
}

// ================================================================================
// Attention kernel: one CTA per batch.
// GEMM1 scores = q @ k^T (bf16 split) -> smem fp32 -> mask+softmax ->
// att to gmem + bf16 hi/lo smem -> GEMM2 ctx = att @ v (v transposed in smem)
// smem map:
//   [0,16K)       q hi    / attHi (GEMM2, 32KB spans q hi+lo)
//   [16K,32K)     q lo
//   [32K,48K)     k hi    / attLo (32KB spans k hi+lo)
//   [48K,64K)     k lo
//   [64K,64K+67584)   scores fp32 [128][132]  / vstag [128][68]
//   [64K+34816, +16K) vbHi [64 rows][256B]
//   [.. +16K)         vbLo
// total = 65536 + 34816 + 16384 + 16384 = 133120 = 65536 + 128*132*4
// ================================================================================
#define ATTN_SMEM (65536 + 128 * 132 * 4)

__global__ __launch_bounds__(256, 1) void attn_tc(
    const float* __restrict__ mask, float* __restrict__ att_out)
{
    extern __shared__ char sm[];
    char*  aHi    = sm;                       // q hi   [128][64]  16KB
    char*  aLo    = sm + 16384;               // q lo
    char*  bHi    = sm + 32768;               // k hi
    char*  bLo    = sm + 49152;               // k lo
    float* scores = (float*)(sm + 65536);     // [128][132] fp32
    char*  attHi  = sm;                       // [128][128] halves, 32KB (aliases q)
    char*  attLo  = sm + 32768;               //                       (aliases k)
    float* vstag  = scores;                   // [128][68] fp32 (aliases scores; stride 272B, 16-aligned)
    char*  vbHi   = sm + 65536 + 34816;       // [64][128] halves 16KB
    char*  vbLo   = sm + 65536 + 34816 + 16384;

    const int b    = blockIdx.x;
    const int tid  = threadIdx.x;
    const int lane = tid & 31;
    const int wid  = tid >> 5;
    const int wm   = wid >> 2;
    const int wn   = wid & 3;
    const int l15  = lane & 15;
    const int l7   = lane & 7;
    const int gA   = lane >> 4;
    const int gB   = (lane >> 3) & 1;

    const float* qb = g_q + (size_t)b * N_ * KDIM_;
    const float* kb = g_k + (size_t)b * N_ * KDIM_;
    const float* vb = g_v + (size_t)b * N_ * HID_;

    const uint32_t aHiB = smem_u32(aHi), bHiB = smem_u32(bHi);
    const uint32_t attHiB = smem_u32(attHi), vbHiB = smem_u32(vbHi);

    // ---------------- GEMM1: scores = q @ k^T ----------------
    uint32_t rowA[4], rowB[4];
    #pragma unroll
    for (int mf = 0; mf < 4; mf++) rowA[mf] = (uint32_t)((wm * 64 + mf * 16 + l15) * 128);
    #pragma unroll
    for (int nf = 0; nf < 4; nf++) rowB[nf] = (uint32_t)((wn * 32 + nf * 8 + l7) * 128);

    float c[4][4][4];
    #pragma unroll
    for (int i = 0; i < 4; i++)
        #pragma unroll
        for (int j = 0; j < 4; j++)
            #pragma unroll
            for (int t = 0; t < 4; t++) c[i][j][t] = 0.f;

    for (int ch = 0; ch < 8; ch++) {
        #pragma unroll
        for (int i = 0; i < 4; i++) {
            int G = tid + i * 256;
            int m = G >> 3, g = G & 7;
            uint32_t off = (uint32_t)(m * 128 + ((g ^ (m & 7)) << 4));
            {
                const float* p = qb + (size_t)m * KDIM_ + ch * 64 + g * 8;
                float4 v0 = *(const float4*)p, v1 = *(const float4*)(p + 4);
                uint4 hi, lo;
                hi.x = pack_hilo(v0.x, v0.y, lo.x);
                hi.y = pack_hilo(v0.z, v0.w, lo.y);
                hi.z = pack_hilo(v1.x, v1.y, lo.z);
                hi.w = pack_hilo(v1.z, v1.w, lo.w);
                *(uint4*)(aHi + off) = hi; *(uint4*)(aLo + off) = lo;
            }
            {
                const float* p = kb + (size_t)m * KDIM_ + ch * 64 + g * 8;
                float4 v0 = *(const float4*)p, v1 = *(const float4*)(p + 4);
                uint4 hi, lo;
                hi.x = pack_hilo(v0.x, v0.y, lo.x);
                hi.y = pack_hilo(v0.z, v0.w, lo.y);
                hi.z = pack_hilo(v1.x, v1.y, lo.z);
                hi.w = pack_hilo(v1.z, v1.w, lo.w);
                *(uint4*)(bHi + off) = hi; *(uint4*)(bLo + off) = lo;
            }
        }
        __syncthreads();
        #pragma unroll
        for (int ks = 0; ks < 4; ks++) {
            uint32_t pa = (uint32_t)((((ks << 1) + gA) ^ l7) << 4);
            uint32_t pb = (uint32_t)((((ks << 1) + gB) ^ l7) << 4);
            uint32_t a[4][4], bf[4][2];
            #pragma unroll
            for (int mf = 0; mf < 4; mf++) ldm_x4(a[mf], aHiB + rowA[mf] + pa);
            #pragma unroll
            for (int nf = 0; nf < 4; nf++) ldm_x2(bf[nf], bHiB + rowB[nf] + pb);
            #pragma unroll
            for (int mf = 0; mf < 4; mf++)
                #pragma unroll
                for (int nf = 0; nf < 4; nf++) mma_bf16(c[mf][nf], a[mf], bf[nf]);
            #pragma unroll
            for (int nf = 0; nf < 4; nf++) ldm_x2(bf[nf], bHiB + 16384 + rowB[nf] + pb);
            #pragma unroll
            for (int mf = 0; mf < 4; mf++)
                #pragma unroll
                for (int nf = 0; nf < 4; nf++) mma_bf16(c[mf][nf], a[mf], bf[nf]);
            #pragma unroll
            for (int mf = 0; mf < 4; mf++) ldm_x4(a[mf], aHiB + 16384 + rowA[mf] + pa);
            #pragma unroll
            for (int nf = 0; nf < 4; nf++) ldm_x2(bf[nf], bHiB + rowB[nf] + pb);
            #pragma unroll
            for (int mf = 0; mf < 4; mf++)
                #pragma unroll
                for (int nf = 0; nf < 4; nf++) mma_bf16(c[mf][nf], a[mf], bf[nf]);
        }
        __syncthreads();
    }

    // ---- write score fragments to smem ----
    #pragma unroll
    for (int mf = 0; mf < 4; mf++) {
        int row = wm * 64 + mf * 16 + (lane >> 2);
        #pragma unroll
        for (int nf = 0; nf < 4; nf++) {
            int col = wn * 32 + nf * 8 + ((lane & 3) << 1);
            *(float2*)(scores + row * 132 + col)       = make_float2(c[mf][nf][0], c[mf][nf][1]);
            *(float2*)(scores + (row + 8) * 132 + col) = make_float2(c[mf][nf][2], c[mf][nf][3]);
        }
    }
    __syncthreads();

    // ---- mask + softmax (one thread per row) + emit att (gmem fp32, smem bf16 split) ----
    if (tid < 128) {
        int r = tid;
        float* srow = scores + r * 132;
        const float* mrow = mask + (size_t)b * N_ * N_ + (size_t)r * N_;
        float mx = -1e30f;
        #pragma unroll 8
        for (int c4 = 0; c4 < 32; c4++) {
            float4 s = *(float4*)(srow + c4 * 4);
            float4 mk = *(const float4*)(mrow + c4 * 4);
            s.x = mk.x * (s.x + 1000.f) - 1000.f;
            s.y = mk.y * (s.y + 1000.f) - 1000.f;
            s.z = mk.z * (s.z + 1000.f) - 1000.f;
            s.w = mk.w * (s.w + 1000.f) - 1000.f;
            *(float4*)(srow + c4 * 4) = s;
            mx = fmaxf(mx, fmaxf(fmaxf(s.x, s.y), fmaxf(s.z, s.w)));
        }
        float sum = 0.f;
        #pragma unroll 8
        for (int c4 = 0; c4 < 32; c4++) {
            float4 s = *(float4*)(srow + c4 * 4);
            s.x = __expf(s.x - mx); s.y = __expf(s.y - mx);
            s.z = __expf(s.z - mx); s.w = __expf(s.w - mx);
            *(float4*)(srow + c4 * 4) = s;
            sum += s.x + s.y + s.z + s.w;
        }
        float inv = 1.f / sum;
        float* arow = att_out + (size_t)b * N_ * N_ + (size_t)r * N_;
        int xr = (r & 7);
        #pragma unroll 8
        for (int c4 = 0; c4 < 32; c4++) {
            int cc = c4 * 4;
            float4 s = *(float4*)(srow + cc);
            float4 a = {s.x * inv, s.y * inv, s.z * inv, s.w * inv};
            *(float4*)(arow + cc) = a;
            uint2 hi, lo;
            hi.x = pack_hilo(a.x, a.y, lo.x);
            hi.y = pack_hilo(a.z, a.w, lo.y);
            uint32_t off = (uint32_t)(r * 256 + (((cc >> 3) ^ xr) << 4) + ((cc & 7) << 1));
            *(uint2*)(attHi + off) = hi;
            *(uint2*)(attLo + off) = lo;
        }
    }
    __syncthreads();

    // ---------------- GEMM2: ctx = att @ v  (N=256 in 4 chunks of 64) ----------------
    uint32_t rowA2[4], rowB2[2];
    #pragma unroll
    for (int mf = 0; mf < 4; mf++) rowA2[mf] = (uint32_t)((wm * 64 + mf * 16 + l15) * 256);
    #pragma unroll
    for (int nf = 0; nf < 2; nf++) rowB2[nf] = (uint32_t)((wn * 16 + nf * 8 + l7) * 256);

    float* cbase = g_ctx + (size_t)b * N_ * HID_;

    for (int hc = 0; hc < 4; hc++) {
        int h0 = hc * 64;
        // stage v chunk [128][64] fp32 (stride 68 floats = 272B, 16-aligned)
        #pragma unroll
        for (int i = 0; i < 8; i++) {
            int id = tid + i * 256;
            int mk = id >> 4, hq = (id & 15) << 2;
            *(float4*)(vstag + mk * 68 + hq) =
                *(const float4*)(vb + (size_t)mk * HID_ + h0 + hq);
        }
        __syncthreads();
        // transpose+convert: vB[n][mk]
        {
            int n = tid & 63;
            int kseg = tid >> 6;              // 0..3
            #pragma unroll
            for (int j = 0; j < 4; j++) {
                int g = kseg * 4 + j;
                int kbase = g * 8;
                float v[8];
                #pragma unroll
                for (int t = 0; t < 8; t++) v[t] = vstag[(kbase + t) * 68 + n];
                uint4 hi, lo;
                hi.x = pack_hilo(v[0], v[1], lo.x);
                hi.y = pack_hilo(v[2], v[3], lo.y);
                hi.z = pack_hilo(v[4], v[5], lo.z);
                hi.w = pack_hilo(v[6], v[7], lo.w);
                uint32_t off = (uint32_t)(n * 256 + ((g ^ (n & 7)) << 4));
                *(uint4*)(vbHi + off) = hi;
                *(uint4*)(vbLo + off) = lo;
            }
        }
        __syncthreads();

        float d[4][2][4];
        #pragma unroll
        for (int i = 0; i < 4; i++)
            #pragma unroll
            for (int j = 0; j < 2; j++)
                #pragma unroll
                for (int t = 0; t < 4; t++) d[i][j][t] = 0.f;

        #pragma unroll
        for (int ks = 0; ks < 8; ks++) {
            uint32_t pa = (uint32_t)((((ks << 1) + gA) ^ l7) << 4);
            uint32_t pb = (uint32_t)((((ks << 1) + gB) ^ l7) << 4);
            uint32_t a[4][4], bf[2][2];
            #pragma unroll
            for (int mf = 0; mf < 4; mf++) ldm_x4(a[mf], attHiB + rowA2[mf] + pa);
            #pragma unroll
            for (int nf = 0; nf < 2; nf++) ldm_x2(bf[nf], vbHiB + rowB2[nf] + pb);
            #pragma unroll
            for (int mf = 0; mf < 4; mf++)
                #pragma unroll
                for (int nf = 0; nf < 2; nf++) mma_bf16(d[mf][nf], a[mf], bf[nf]);
            #pragma unroll
            for (int nf = 0; nf < 2; nf++) ldm_x2(bf[nf], vbHiB + 16384 + rowB2[nf] + pb);
            #pragma unroll
            for (int mf = 0; mf < 4; mf++)
                #pragma unroll
                for (int nf = 0; nf < 2; nf++) mma_bf16(d[mf][nf], a[mf], bf[nf]);
            #pragma unroll
            for (int mf = 0; mf < 4; mf++) ldm_x4(a[mf], attHiB + 32768 + rowA2[mf] + pa);
            #pragma unroll
            for (int nf = 0; nf < 2; nf++) ldm_x2(bf[nf], vbHiB + rowB2[nf] + pb);
            #pragma unroll
            for (int mf = 0; mf < 4; mf++)
                #pragma unroll
                for (int nf = 0; nf < 2; nf++) mma_bf16(d[mf][nf], a[mf], bf[nf]);
        }

        // epilogue: ctx fp32
        #pragma unroll
        for (int mf = 0; mf < 4; mf++) {
            int row = wm * 64 + mf * 16 + (lane >> 2);
            #pragma unroll
            for (int nf = 0; nf < 2; nf++) {
                int col = h0 + wn * 16 + nf * 8 + ((lane & 3) << 1);
                *(float2*)(cbase + (size_t)row * HID_ + col) =
                    make_float2(d[mf][nf][0], d[mf][nf][1]);
                *(float2*)(cbase + (size_t)(row + 8) * HID_ + col) =
                    make_float2(d[mf][nf][2], d[mf][nf][3]);
            }
        }
        __syncthreads();
    }
}

// ================================================================================
// Launch
// ================================================================================
extern "C" void kernel_launch(void* const* d_in, const int* in_sizes, int n_in,
                              void* d_out, int out_size)
{
    const float* x    = (const float*)d_in[0];
    const float* mask = (const float*)d_in[1];
    const float* Wv   = (const float*)d_in[2];
    const float* bv   = (const float*)d_in[3];
    const float* Wq   = (const float*)d_in[4];
    const float* bq   = (const float*)d_in[5];
    const float* Wk   = (const float*)d_in[6];
    const float* bk   = (const float*)d_in[7];
    const float* Wo   = (const float*)d_in[8];
    const float* bo   = (const float*)d_in[9];

    float* out     = (float*)d_out;
    float* att_out = out + (size_t)B_ * N_ * DOUT_;

    cudaFuncSetAttribute(qkv_tc,  cudaFuncAttributeMaxDynamicSharedMemorySize, PROJ_SMEM);
    cudaFuncSetAttribute(out_tc,  cudaFuncAttributeMaxDynamicSharedMemorySize, PROJ_SMEM);
    cudaFuncSetAttribute(attn_tc, cudaFuncAttributeMaxDynamicSharedMemorySize, ATTN_SMEM);

    qkv_tc<<<dim3(10, 1024), 256, PROJ_SMEM>>>(x, Wv, bv, Wq, bq, Wk, bk);
    attn_tc<<<1024, 256, ATTN_SMEM>>>(mask, att_out);
    out_tc<<<dim3(2, 1024), 256, PROJ_SMEM>>>(Wo, bo, out);
}

// round 5
// speedup vs baseline: 2.7616x; 1.1798x over previous
#include <cuda_runtime.h>
#include <cuda_bf16.h>
#include <cstdint>

#define B_    1024
#define N_    128
#define DIN_  256
#define HID_  256
#define DOUT_ 256
#define KDIM_ 512

#define TILE_B 16384   // one [128 rows][64 k] split-bf16 tile (swizzled)

// ---------------- scratch (static device globals; no allocation) ----------------
__device__ unsigned char g_xhi[(size_t)1024 * 4 * TILE_B];
__device__ unsigned char g_xlo[(size_t)1024 * 4 * TILE_B];
__device__ unsigned char g_whi[(size_t)12 * 4 * TILE_B];
__device__ unsigned char g_wlo[(size_t)12 * 4 * TILE_B];
__device__ unsigned char g_qhi[(size_t)1024 * 8 * TILE_B];
__device__ unsigned char g_qlo[(size_t)1024 * 8 * TILE_B];
__device__ unsigned char g_khi[(size_t)1024 * 8 * TILE_B];
__device__ unsigned char g_klo[(size_t)1024 * 8 * TILE_B];
__device__ unsigned char g_chi[(size_t)1024 * 4 * TILE_B];
__device__ unsigned char g_clo[(size_t)1024 * 4 * TILE_B];
__device__ float g_v[(size_t)B_ * N_ * HID_];

// ================================================================================
// helpers
// ================================================================================
__device__ __forceinline__ uint32_t smem_u32(const void* p) {
    uint32_t a;
    asm("{ .reg .u64 t; cvta.to.shared.u64 t, %1; cvt.u32.u64 %0, t; }" : "=r"(a) : "l"(p));
    return a;
}
__device__ __forceinline__ void ldm_x4(uint32_t* r, uint32_t addr) {
    asm volatile("ldmatrix.sync.aligned.m8n8.x4.shared.b16 {%0,%1,%2,%3}, [%4];"
                 : "=r"(r[0]), "=r"(r[1]), "=r"(r[2]), "=r"(r[3]) : "r"(addr));
}
__device__ __forceinline__ void ldm_x2(uint32_t* r, uint32_t addr) {
    asm volatile("ldmatrix.sync.aligned.m8n8.x2.shared.b16 {%0,%1}, [%2];"
                 : "=r"(r[0]), "=r"(r[1]) : "r"(addr));
}
__device__ __forceinline__ void mma_bf16(float* c, const uint32_t* a, const uint32_t* b) {
    asm volatile(
        "mma.sync.aligned.m16n8k16.row.col.f32.bf16.bf16.f32 "
        "{%0,%1,%2,%3}, {%4,%5,%6,%7}, {%8,%9}, {%0,%1,%2,%3};"
        : "+f"(c[0]), "+f"(c[1]), "+f"(c[2]), "+f"(c[3])
        : "r"(a[0]), "r"(a[1]), "r"(a[2]), "r"(a[3]), "r"(b[0]), "r"(b[1]));
}
__device__ __forceinline__ uint32_t pack_hilo(float x, float y, uint32_t& lo_out) {
    __nv_bfloat162 h = __floats2bfloat162_rn(x, y);
    float lx = x - __low2float(h);
    float ly = y - __high2float(h);
    __nv_bfloat162 l = __floats2bfloat162_rn(lx, ly);
    lo_out = *reinterpret_cast<uint32_t*>(&l);
    return *reinterpret_cast<uint32_t*>(&h);
}
// byte offset inside one swizzled tile: row 0..127, k 0..63
__device__ __forceinline__ uint32_t tile_off(int row, int k) {
    int g = k >> 3;
    return (uint32_t)(row * 128 + ((g ^ (row & 7)) << 4) + ((k & 7) << 1));
}

#define CP16(dst_s, src_g) \
    asm volatile("cp.async.cg.shared.global [%0], [%1], 16;" :: "r"(dst_s), "l"(src_g) : "memory")
#define CP_COMMIT() asm volatile("cp.async.commit_group;" ::: "memory")
#define CP_WAIT0()  asm volatile("cp.async.wait_group 0;" ::: "memory")
#define CP_WAIT1()  asm volatile("cp.async.wait_group 1;" ::: "memory")

// ================================================================================
// split_x: x fp32 -> per-(mt,ch) swizzled split-bf16 tiles
// ================================================================================
__global__ __launch_bounds__(256) void split_x_kernel(const float* __restrict__ x)
{
    const int mt = blockIdx.x, tid = threadIdx.x;
    const float* A = x + (size_t)mt * 128 * DIN_;
    unsigned char* dh = g_xhi + (size_t)mt * 4 * TILE_B;
    unsigned char* dl = g_xlo + (size_t)mt * 4 * TILE_B;
    #pragma unroll
    for (int i = 0; i < 16; i++) {
        int G = tid + i * 256;
        int m = G >> 5, gg = G & 31;
        int ch = gg >> 3, g = gg & 7;
        const float* p = A + (size_t)m * DIN_ + gg * 8;
        float4 v0 = *(const float4*)p, v1 = *(const float4*)(p + 4);
        uint4 hi, lo;
        hi.x = pack_hilo(v0.x, v0.y, lo.x);
        hi.y = pack_hilo(v0.z, v0.w, lo.y);
        hi.z = pack_hilo(v1.x, v1.y, lo.z);
        hi.w = pack_hilo(v1.z, v1.w, lo.w);
        uint32_t off = (uint32_t)(ch * TILE_B + m * 128 + ((g ^ (m & 7)) << 4));
        *(uint4*)(dh + off) = hi;
        *(uint4*)(dl + off) = lo;
    }
}

// ================================================================================
// split_w: W[k][n] -> transposed K-major swizzled split-bf16 tiles.
// tiles: 0-1 Wv, 2-5 Wq, 6-9 Wk, 10-11 Wo.
// ================================================================================
__global__ __launch_bounds__(256) void split_w_kernel(
    const float* __restrict__ Wv, const float* __restrict__ Wq,
    const float* __restrict__ Wk, const float* __restrict__ Wo)
{
    __shared__ float wst[64 * 132];
    const int tt = blockIdx.x, tid = threadIdx.x;
    const float* W; int wld, c0;
    if (tt < 2)       { W = Wv; wld = HID_;  c0 = tt * 128; }
    else if (tt < 6)  { W = Wq; wld = KDIM_; c0 = (tt - 2) * 128; }
    else if (tt < 10) { W = Wk; wld = KDIM_; c0 = (tt - 6) * 128; }
    else              { W = Wo; wld = DOUT_; c0 = (tt - 10) * 128; }

    unsigned char* dh = g_whi + (size_t)tt * 4 * TILE_B;
    unsigned char* dl = g_wlo + (size_t)tt * 4 * TILE_B;

    for (int ch = 0; ch < 4; ch++) {
        #pragma unroll
        for (int i = 0; i < 8; i++) {
            int idx = tid + i * 256;
            int kr = idx >> 5, nq = (idx & 31) << 2;
            *(float4*)(wst + kr * 132 + nq) =
                *(const float4*)(W + (size_t)(ch * 64 + kr) * wld + c0 + nq);
        }
        __syncthreads();
        {
            int n = tid & 127, ks2 = tid >> 7;
            #pragma unroll
            for (int j = 0; j < 4; j++) {
                int g = ks2 * 4 + j, kb = g * 8;
                float v[8];
                #pragma unroll
                for (int t = 0; t < 8; t++) v[t] = wst[(kb + t) * 132 + n];
                uint4 hi, lo;
                hi.x = pack_hilo(v[0], v[1], lo.x);
                hi.y = pack_hilo(v[2], v[3], lo.y);
                hi.z = pack_hilo(v[4], v[5], lo.z);
                hi.w = pack_hilo(v[6], v[7], lo.w);
                uint32_t off = (uint32_t)(ch * TILE_B + n * 128 + ((g ^ (n & 7)) << 4));
                *(uint4*)(dh + off) = hi;
                *(uint4*)(dl + off) = lo;
            }
        }
        __syncthreads();
    }
}

// ================================================================================
// Core 128x128 MMA block (declared as macro-ish inline): 4 k16-steps x 3 passes.
// buffers at base: aHi | aLo(+16K) | bHi(+32K) | bLo(+48K)
// ================================================================================
struct Frag { float c[4][4][4]; };

__device__ __forceinline__ void mma_chunk(uint32_t base, const uint32_t* rowA,
                                          const uint32_t* rowB, int gA, int gB, int l7,
                                          Frag& F)
{
    #pragma unroll
    for (int ks = 0; ks < 4; ks++) {
        uint32_t pa = (uint32_t)((((ks << 1) + gA) ^ l7) << 4);
        uint32_t pb = (uint32_t)((((ks << 1) + gB) ^ l7) << 4);
        uint32_t a[4][4], b[4][2];
        #pragma unroll
        for (int mf = 0; mf < 4; mf++) ldm_x4(a[mf], base + rowA[mf] + pa);
        #pragma unroll
        for (int nf = 0; nf < 4; nf++) ldm_x2(b[nf], base + 32768 + rowB[nf] + pb);
        #pragma unroll
        for (int mf = 0; mf < 4; mf++)
            #pragma unroll
            for (int nf = 0; nf < 4; nf++) mma_bf16(F.c[mf][nf], a[mf], b[nf]);
        #pragma unroll
        for (int nf = 0; nf < 4; nf++) ldm_x2(b[nf], base + 49152 + rowB[nf] + pb);
        #pragma unroll
        for (int mf = 0; mf < 4; mf++)
            #pragma unroll
            for (int nf = 0; nf < 4; nf++) mma_bf16(F.c[mf][nf], a[mf], b[nf]);
        #pragma unroll
        for (int mf = 0; mf < 4; mf++) ldm_x4(a[mf], base + 16384 + rowA[mf] + pa);
        #pragma unroll
        for (int nf = 0; nf < 4; nf++) ldm_x2(b[nf], base + 32768 + rowB[nf] + pb);
        #pragma unroll
        for (int mf = 0; mf < 4; mf++)
            #pragma unroll
            for (int nf = 0; nf < 4; nf++) mma_bf16(F.c[mf][nf], a[mf], b[nf]);
    }
}

// ================================================================================
// qkv: grid (10, 1024). copies pre-split tiles, MMA, epilogue:
//   nt<2  -> v fp32
//   else  -> q/k split-bf16 tiles (attn layout)
// ================================================================================
__global__ __launch_bounds__(256, 2) void qkv_tc(
    const float* __restrict__ bv, const float* __restrict__ bq, const float* __restrict__ bk)
{
    extern __shared__ char sm[];
    const int nt = blockIdx.x, mt = blockIdx.y;
    const int tid = threadIdx.x, lane = tid & 31, wid = tid >> 5;
    const int wm = wid >> 2, wn = wid & 3;
    const int l15 = lane & 15, l7 = lane & 7;
    const int gA = lane >> 4, gB = (lane >> 3) & 1;

    const uint32_t base = smem_u32(sm);

    uint32_t rowA[4], rowB[4];
    #pragma unroll
    for (int mf = 0; mf < 4; mf++) rowA[mf] = (uint32_t)((wm * 64 + mf * 16 + l15) * 128);
    #pragma unroll
    for (int nf = 0; nf < 4; nf++) rowB[nf] = (uint32_t)((wn * 32 + nf * 8 + l7) * 128);

    Frag F;
    #pragma unroll
    for (int i = 0; i < 4; i++)
        #pragma unroll
        for (int j = 0; j < 4; j++)
            #pragma unroll
            for (int t = 0; t < 4; t++) F.c[i][j][t] = 0.f;

    for (int ch = 0; ch < 4; ch++) {
        const unsigned char* sAh = g_xhi + ((size_t)mt * 4 + ch) * TILE_B;
        const unsigned char* sAl = g_xlo + ((size_t)mt * 4 + ch) * TILE_B;
        const unsigned char* sBh = g_whi + ((size_t)nt * 4 + ch) * TILE_B;
        const unsigned char* sBl = g_wlo + ((size_t)nt * 4 + ch) * TILE_B;
        #pragma unroll
        for (int j = 0; j < 4; j++) {
            uint32_t o = (uint32_t)((tid + j * 256) * 16);
            CP16(base + o,         sAh + o);
            CP16(base + 16384 + o, sAl + o);
            CP16(base + 32768 + o, sBh + o);
            CP16(base + 49152 + o, sBl + o);
        }
        CP_COMMIT();
        CP_WAIT0();
        __syncthreads();
        mma_chunk(base, rowA, rowB, gA, gB, l7, F);
        __syncthreads();
    }

    if (nt < 2) {
        float* O = g_v + (size_t)mt * 128 * HID_;
        int c0 = nt * 128;
        #pragma unroll
        for (int mf = 0; mf < 4; mf++) {
            int row = wm * 64 + mf * 16 + (lane >> 2);
            #pragma unroll
            for (int nf = 0; nf < 4; nf++) {
                int col = c0 + wn * 32 + nf * 8 + ((lane & 3) << 1);
                float b0 = __ldg(bv + col), b1 = __ldg(bv + col + 1);
                float2 o0 = {fmaxf(F.c[mf][nf][0] + b0, 0.f), fmaxf(F.c[mf][nf][1] + b1, 0.f)};
                float2 o1 = {fmaxf(F.c[mf][nf][2] + b0, 0.f), fmaxf(F.c[mf][nf][3] + b1, 0.f)};
                *(float2*)(O + (size_t)row * HID_ + col)       = o0;
                *(float2*)(O + (size_t)(row + 8) * HID_ + col) = o1;
            }
        }
    } else {
        const bool isq = nt < 6;
        unsigned char* dh = (isq ? g_qhi : g_khi) + (size_t)mt * 8 * TILE_B;
        unsigned char* dl = (isq ? g_qlo : g_klo) + (size_t)mt * 8 * TILE_B;
        const float* bias = isq ? bq : bk;
        int c0k = (isq ? (nt - 2) : (nt - 6)) * 128;
        #pragma unroll
        for (int mf = 0; mf < 4; mf++) {
            int row = wm * 64 + mf * 16 + (lane >> 2);
            #pragma unroll
            for (int nf = 0; nf < 4; nf++) {
                int col = c0k + wn * 32 + nf * 8 + ((lane & 3) << 1);
                float b0 = __ldg(bias + col), b1 = __ldg(bias + col + 1);
                float r0 = fmaxf(F.c[mf][nf][0] + b0, 0.f);
                float r1 = fmaxf(F.c[mf][nf][1] + b1, 0.f);
                float r2 = fmaxf(F.c[mf][nf][2] + b0, 0.f);
                float r3 = fmaxf(F.c[mf][nf][3] + b1, 0.f);
                int ch = col >> 6, kloc = col & 63;
                size_t tb = (size_t)ch * TILE_B;
                uint32_t lo0, hi0 = pack_hilo(r0, r1, lo0);
                uint32_t o0 = tile_off(row, kloc);
                *(uint32_t*)(dh + tb + o0) = hi0;
                *(uint32_t*)(dl + tb + o0) = lo0;
                uint32_t lo1, hi1 = pack_hilo(r2, r3, lo1);
                uint32_t o1 = tile_off(row + 8, kloc);
                *(uint32_t*)(dh + tb + o1) = hi1;
                *(uint32_t*)(dl + tb + o1) = lo1;
            }
        }
    }
}

// ================================================================================
// out: grid (2, 1024). A from ctx split tiles, B from Wo tiles (tt = 10+nt).
// ================================================================================
__global__ __launch_bounds__(256, 2) void out_tc(
    const float* __restrict__ bo, float* __restrict__ out)
{
    extern __shared__ char sm[];
    const int nt = blockIdx.x, mt = blockIdx.y;
    const int tid = threadIdx.x, lane = tid & 31, wid = tid >> 5;
    const int wm = wid >> 2, wn = wid & 3;
    const int l15 = lane & 15, l7 = lane & 7;
    const int gA = lane >> 4, gB = (lane >> 3) & 1;

    const uint32_t base = smem_u32(sm);

    uint32_t rowA[4], rowB[4];
    #pragma unroll
    for (int mf = 0; mf < 4; mf++) rowA[mf] = (uint32_t)((wm * 64 + mf * 16 + l15) * 128);
    #pragma unroll
    for (int nf = 0; nf < 4; nf++) rowB[nf] = (uint32_t)((wn * 32 + nf * 8 + l7) * 128);

    Frag F;
    #pragma unroll
    for (int i = 0; i < 4; i++)
        #pragma unroll
        for (int j = 0; j < 4; j++)
            #pragma unroll
            for (int t = 0; t < 4; t++) F.c[i][j][t] = 0.f;

    for (int ch = 0; ch < 4; ch++) {
        const unsigned char* sAh = g_chi + ((size_t)mt * 4 + ch) * TILE_B;
        const unsigned char* sAl = g_clo + ((size_t)mt * 4 + ch) * TILE_B;
        const unsigned char* sBh = g_whi + ((size_t)(10 + nt) * 4 + ch) * TILE_B;
        const unsigned char* sBl = g_wlo + ((size_t)(10 + nt) * 4 + ch) * TILE_B;
        #pragma unroll
        for (int j = 0; j < 4; j++) {
            uint32_t o = (uint32_t)((tid + j * 256) * 16);
            CP16(base + o,         sAh + o);
            CP16(base + 16384 + o, sAl + o);
            CP16(base + 32768 + o, sBh + o);
            CP16(base + 49152 + o, sBl + o);
        }
        CP_COMMIT();
        CP_WAIT0();
        __syncthreads();
        mma_chunk(base, rowA, rowB, gA, gB, l7, F);
        __syncthreads();
    }

    int c0 = nt * 128;
    #pragma unroll
    for (int mf = 0; mf < 4; mf++) {
        int row = wm * 64 + mf * 16 + (lane >> 2);
        #pragma unroll
        for (int nf = 0; nf < 4; nf++) {
            int col = c0 + wn * 32 + nf * 8 + ((lane & 3) << 1);
            float b0 = __ldg(bo + col), b1 = __ldg(bo + col + 1);
            float2 o0 = {fmaxf(F.c[mf][nf][0] + b0, 0.f), fmaxf(F.c[mf][nf][1] + b1, 0.f)};
            float2 o1 = {fmaxf(F.c[mf][nf][2] + b0, 0.f), fmaxf(F.c[mf][nf][3] + b1, 0.f)};
            *(float2*)(out + (size_t)(mt * 128 + row) * DOUT_ + col)       = o0;
            *(float2*)(out + (size_t)(mt * 128 + row + 8) * DOUT_ + col)   = o1;
        }
    }
}

// ================================================================================
// attn: one CTA/batch. GEMM1 double-buffered cp.async pipeline over 8 chunks.
// smem map (dynamic, 198656 B):
//   [0,64K)        stage set0: aHi|aLo|bHi|bLo (16KB each)
//   [64K,128K)     stage set1
//   [128K, +67584) scores fp32 [128][132]   (aliases vstag [128][68])
// GEMM2 aliases: attHi=[0,32K) attLo=[32K,64K) vbHi=[64K,80K) vbLo=[80K,96K)
// ================================================================================
#define ATTN_SMEM (131072 + 128 * 132 * 4)

__global__ __launch_bounds__(256, 1) void attn_tc(
    const float* __restrict__ mask, float* __restrict__ att_out)
{
    extern __shared__ char sm[];
    float* scores = (float*)(sm + 131072);
    char*  attHi  = sm;
    char*  attLo  = sm + 32768;
    float* vstag  = scores;
    char*  vbHi   = sm + 65536;
    char*  vbLo   = sm + 81920;

    const int b = blockIdx.x;
    const int tid = threadIdx.x, lane = tid & 31, wid = tid >> 5;
    const int wm = wid >> 2, wn = wid & 3;
    const int l15 = lane & 15, l7 = lane & 7;
    const int gA = lane >> 4, gB = (lane >> 3) & 1;

    const uint32_t S0 = smem_u32(sm);
    const uint32_t attHiB = S0, vbHiB = S0 + 65536;

    const unsigned char* qh = g_qhi + (size_t)b * 8 * TILE_B;
    const unsigned char* ql = g_qlo + (size_t)b * 8 * TILE_B;
    const unsigned char* kh = g_khi + (size_t)b * 8 * TILE_B;
    const unsigned char* kl = g_klo + (size_t)b * 8 * TILE_B;
    const float* vb = g_v + (size_t)b * N_ * HID_;

    uint32_t rowA[4], rowB[4];
    #pragma unroll
    for (int mf = 0; mf < 4; mf++) rowA[mf] = (uint32_t)((wm * 64 + mf * 16 + l15) * 128);
    #pragma unroll
    for (int nf = 0; nf < 4; nf++) rowB[nf] = (uint32_t)((wn * 32 + nf * 8 + l7) * 128);

    Frag F;
    #pragma unroll
    for (int i = 0; i < 4; i++)
        #pragma unroll
        for (int j = 0; j < 4; j++)
            #pragma unroll
            for (int t = 0; t < 4; t++) F.c[i][j][t] = 0.f;

    // prologue copy ch0 -> set0
    {
        #pragma unroll
        for (int j = 0; j < 4; j++) {
            uint32_t o = (uint32_t)((tid + j * 256) * 16);
            CP16(S0 + o,         qh + o);
            CP16(S0 + 16384 + o, ql + o);
            CP16(S0 + 32768 + o, kh + o);
            CP16(S0 + 49152 + o, kl + o);
        }
        CP_COMMIT();
    }

    for (int ch = 0; ch < 8; ch++) {
        __syncthreads();   // MMA(ch-1) done everywhere before overwriting its set
        if (ch < 7) {
            uint32_t nbase = S0 + (uint32_t)(((ch + 1) & 1) * 65536);
            size_t src = (size_t)(ch + 1) * TILE_B;
            #pragma unroll
            for (int j = 0; j < 4; j++) {
                uint32_t o = (uint32_t)((tid + j * 256) * 16);
                CP16(nbase + o,         qh + src + o);
                CP16(nbase + 16384 + o, ql + src + o);
                CP16(nbase + 32768 + o, kh + src + o);
                CP16(nbase + 49152 + o, kl + src + o);
            }
            CP_COMMIT();
            CP_WAIT1();    // chunk ch resident; ch+1 in flight
        } else {
            CP_WAIT0();
        }
        __syncthreads();
        mma_chunk(S0 + (uint32_t)((ch & 1) * 65536), rowA, rowB, gA, gB, l7, F);
    }
    __syncthreads();

    // ---- fragments -> scores smem ----
    #pragma unroll
    for (int mf = 0; mf < 4; mf++) {
        int row = wm * 64 + mf * 16 + (lane >> 2);
        #pragma unroll
        for (int nf = 0; nf < 4; nf++) {
            int col = wn * 32 + nf * 8 + ((lane & 3) << 1);
            *(float2*)(scores + row * 132 + col)       = make_float2(F.c[mf][nf][0], F.c[mf][nf][1]);
            *(float2*)(scores + (row + 8) * 132 + col) = make_float2(F.c[mf][nf][2], F.c[mf][nf][3]);
        }
    }
    __syncthreads();

    // ---- mask + softmax + emit att (gmem fp32, smem split-bf16) ----
    if (tid < 128) {
        int r = tid;
        float* srow = scores + r * 132;
        const float* mrow = mask + (size_t)b * N_ * N_ + (size_t)r * N_;
        float mx = -1e30f;
        #pragma unroll 8
        for (int c4 = 0; c4 < 32; c4++) {
            float4 s = *(float4*)(srow + c4 * 4);
            float4 mk = *(const float4*)(mrow + c4 * 4);
            s.x = mk.x * (s.x + 1000.f) - 1000.f;
            s.y = mk.y * (s.y + 1000.f) - 1000.f;
            s.z = mk.z * (s.z + 1000.f) - 1000.f;
            s.w = mk.w * (s.w + 1000.f) - 1000.f;
            *(float4*)(srow + c4 * 4) = s;
            mx = fmaxf(mx, fmaxf(fmaxf(s.x, s.y), fmaxf(s.z, s.w)));
        }
        float sum = 0.f;
        #pragma unroll 8
        for (int c4 = 0; c4 < 32; c4++) {
            float4 s = *(float4*)(srow + c4 * 4);
            s.x = __expf(s.x - mx); s.y = __expf(s.y - mx);
            s.z = __expf(s.z - mx); s.w = __expf(s.w - mx);
            *(float4*)(srow + c4 * 4) = s;
            sum += s.x + s.y + s.z + s.w;
        }
        float inv = 1.f / sum;
        float* arow = att_out + (size_t)b * N_ * N_ + (size_t)r * N_;
        int xr = (r & 7);
        #pragma unroll 8
        for (int c4 = 0; c4 < 32; c4++) {
            int cc = c4 * 4;
            float4 s = *(float4*)(srow + cc);
            float4 a = {s.x * inv, s.y * inv, s.z * inv, s.w * inv};
            *(float4*)(arow + cc) = a;
            uint2 hi, lo;
            hi.x = pack_hilo(a.x, a.y, lo.x);
            hi.y = pack_hilo(a.z, a.w, lo.y);
            uint32_t off = (uint32_t)(r * 256 + (((cc >> 3) ^ xr) << 4) + ((cc & 7) << 1));
            *(uint2*)(attHi + off) = hi;
            *(uint2*)(attLo + off) = lo;
        }
    }
    __syncthreads();

    // ---------------- GEMM2: ctx = att @ v ----------------
    uint32_t rowA2[4], rowB2[2];
    #pragma unroll
    for (int mf = 0; mf < 4; mf++) rowA2[mf] = (uint32_t)((wm * 64 + mf * 16 + l15) * 256);
    #pragma unroll
    for (int nf = 0; nf < 2; nf++) rowB2[nf] = (uint32_t)((wn * 16 + nf * 8 + l7) * 256);

    unsigned char* dch = g_chi + (size_t)b * 4 * TILE_B;
    unsigned char* dcl = g_clo + (size_t)b * 4 * TILE_B;

    for (int hc = 0; hc < 4; hc++) {
        int h0 = hc * 64;
        #pragma unroll
        for (int i = 0; i < 8; i++) {
            int id = tid + i * 256;
            int mk = id >> 4, hq = (id & 15) << 2;
            *(float4*)(vstag + mk * 68 + hq) =
                *(const float4*)(vb + (size_t)mk * HID_ + h0 + hq);
        }
        __syncthreads();
        {
            int n = tid & 63, kseg = tid >> 6;
            #pragma unroll
            for (int j = 0; j < 4; j++) {
                int g = kseg * 4 + j, kb2 = g * 8;
                float v[8];
                #pragma unroll
                for (int t = 0; t < 8; t++) v[t] = vstag[(kb2 + t) * 68 + n];
                uint4 hi, lo;
                hi.x = pack_hilo(v[0], v[1], lo.x);
                hi.y = pack_hilo(v[2], v[3], lo.y);
                hi.z = pack_hilo(v[4], v[5], lo.z);
                hi.w = pack_hilo(v[6], v[7], lo.w);
                uint32_t off = (uint32_t)(n * 256 + ((g ^ (n & 7)) << 4));
                *(uint4*)(vbHi + off) = hi;
                *(uint4*)(vbLo + off) = lo;
            }
        }
        __syncthreads();

        float d[4][2][4];
        #pragma unroll
        for (int i = 0; i < 4; i++)
            #pragma unroll
            for (int j = 0; j < 2; j++)
                #pragma unroll
                for (int t = 0; t < 4; t++) d[i][j][t] = 0.f;

        #pragma unroll
        for (int ks = 0; ks < 8; ks++) {
            uint32_t pa = (uint32_t)((((ks << 1) + gA) ^ l7) << 4);
            uint32_t pb = (uint32_t)((((ks << 1) + gB) ^ l7) << 4);
            uint32_t a[4][4], bf[2][2];
            #pragma unroll
            for (int mf = 0; mf < 4; mf++) ldm_x4(a[mf], attHiB + rowA2[mf] + pa);
            #pragma unroll
            for (int nf = 0; nf < 2; nf++) ldm_x2(bf[nf], vbHiB + rowB2[nf] + pb);
            #pragma unroll
            for (int mf = 0; mf < 4; mf++)
                #pragma unroll
                for (int nf = 0; nf < 2; nf++) mma_bf16(d[mf][nf], a[mf], bf[nf]);
            #pragma unroll
            for (int nf = 0; nf < 2; nf++) ldm_x2(bf[nf], vbHiB + 16384 + rowB2[nf] + pb);
            #pragma unroll
            for (int mf = 0; mf < 4; mf++)
                #pragma unroll
                for (int nf = 0; nf < 2; nf++) mma_bf16(d[mf][nf], a[mf], bf[nf]);
            #pragma unroll
            for (int mf = 0; mf < 4; mf++) ldm_x4(a[mf], attHiB + 32768 + rowA2[mf] + pa);
            #pragma unroll
            for (int nf = 0; nf < 2; nf++) ldm_x2(bf[nf], vbHiB + rowB2[nf] + pb);
            #pragma unroll
            for (int mf = 0; mf < 4; mf++)
                #pragma unroll
                for (int nf = 0; nf < 2; nf++) mma_bf16(d[mf][nf], a[mf], bf[nf]);
        }

        // epilogue: ctx -> split-bf16 tiles
        #pragma unroll
        for (int mf = 0; mf < 4; mf++) {
            int row = wm * 64 + mf * 16 + (lane >> 2);
            #pragma unroll
            for (int nf = 0; nf < 2; nf++) {
                int col = h0 + wn * 16 + nf * 8 + ((lane & 3) << 1);
                int ch = col >> 6, kloc = col & 63;
                size_t tb = (size_t)ch * TILE_B;
                uint32_t lo0, hi0 = pack_hilo(d[mf][nf][0], d[mf][nf][1], lo0);
                uint32_t o0 = tile_off(row, kloc);
                *(uint32_t*)(dch + tb + o0) = hi0;
                *(uint32_t*)(dcl + tb + o0) = lo0;
                uint32_t lo1, hi1 = pack_hilo(d[mf][nf][2], d[mf][nf][3], lo1);
                uint32_t o1 = tile_off(row + 8, kloc);
                *(uint32_t*)(dch + tb + o1) = hi1;
                *(uint32_t*)(dcl + tb + o1) = lo1;
            }
        }
        __syncthreads();
    }
}

// ================================================================================
// Launch
// ================================================================================
extern "C" void kernel_launch(void* const* d_in, const int* in_sizes, int n_in,
                              void* d_out, int out_size)
{
    const float* x    = (const float*)d_in[0];
    const float* mask = (const float*)d_in[1];
    const float* Wv   = (const float*)d_in[2];
    const float* bv   = (const float*)d_in[3];
    const float* Wq   = (const float*)d_in[4];
    const float* bq   = (const float*)d_in[5];
    const float* Wk   = (const float*)d_in[6];
    const float* bk   = (const float*)d_in[7];
    const float* Wo   = (const float*)d_in[8];
    const float* bo   = (const float*)d_in[9];

    float* out     = (float*)d_out;
    float* att_out = out + (size_t)B_ * N_ * DOUT_;

    cudaFuncSetAttribute(qkv_tc,  cudaFuncAttributeMaxDynamicSharedMemorySize, 65536);
    cudaFuncSetAttribute(out_tc,  cudaFuncAttributeMaxDynamicSharedMemorySize, 65536);
    cudaFuncSetAttribute(attn_tc, cudaFuncAttributeMaxDynamicSharedMemorySize, ATTN_SMEM);

    split_x_kernel<<<1024, 256>>>(x);
    split_w_kernel<<<12, 256>>>(Wv, Wq, Wk, Wo);
    qkv_tc<<<dim3(10, 1024), 256, 65536>>>(bv, bq, bk);
    attn_tc<<<1024, 256, ATTN_SMEM>>>(mask, att_out);
    out_tc<<<dim3(2, 1024), 256, 65536>>>(bo, out);
}